// round 14
// baseline (speedup 1.0000x reference)
#include <cuda_runtime.h>

// 16-qubit, 2-layer BasicEntangler QNN — branchless transfer-matrix closed form.
// FINAL — verified stable at the single-launch overhead floor.
//
// Derivation (verified rounds 1-3 against the state-vector path):
//   All circuit generators are X-type and mutually commute. Both CNOT rings
//   (linear GF(2) map F) commute to the ends of the circuit:
//     <Z_w> = <0| Prod_{j in A_w} exp(i theta_j X_{m_j}) |0>
//   masks m: {w} at angle phi_w = x_w + W0_w (embedding + layer-0 fused);
//   b_0={0,1}, b_v={v,v+1} (v=1..14), b_15={0,1,15}  (= F^{-1} e_v);
//   S = R_w = row w of F^2 (R_MASK), absorbing the trailing permutation.
//   The XOR-zero subset sum collapses to a 2-state chain DP over wires; the
//   outer variable t15 (feeding mask bits 0,1,15) gives two chains, one per
//   lane (lane^16 = partner), combined with one shfl.
//
// Perf history: 46.8us (state-vector) -> 19.2us (branchy DP) -> 6.9us
// (branchless multi-SM) -> 6.5us floor. Rounds 5-13: seven materially
// different binaries all land in 6.53-6.88us; kernel-dur noise ~0.6us on
// identical binaries. Remaining time = per-launch overhead at idle DVFS
// clocks + graph replay; body ~0.5us; all pipes <0.3% of peak.

#define NQ 16

__constant__ unsigned int R_MASK[16] = {
    0xAAABu, 0xFFFDu, 0xFFFAu, 0xFFF5u, 0xFFEAu, 0xFFD5u, 0xFFAAu, 0xFF55u,
    0xFEAAu, 0xFD55u, 0xFAAAu, 0xF555u, 0xEAAAu, 0xD555u, 0xAAAAu, 0x5555u
};

__global__ void __launch_bounds__(32)
qnn_final(const float* __restrict__ x, const float* __restrict__ wts,
          float* __restrict__ out) {
    // trig[0]=cos(phi), trig[1]=sin(phi), trig[2]=cos(theta), trig[3]=sin(theta)
    __shared__ float trig[4][NQ];

    const int lane = threadIdx.x;
    const int w    = lane & 15;          // output wire
    const bool isB = lane >= 16;         // chain select (t15 = 1)
    const int b    = blockIdx.x;         // sample (one warp per sample)

    // ---- divergence-free prologue: one sincos per lane, no branch ----
    {
        const float xv  = x[b * NQ + w];
        const float wv  = wts[(isB ? NQ : 0) + w];
        const float ang = isB ? wv : (xv + wv);  // theta : phi = x + W0
        float s, c;
        __sincosf(ang, &s, &c);
        const int r = isB ? 2 : 0;
        trig[r][w]     = c;
        trig[r + 1][w] = s;
    }
    __syncwarp();

    const float* cph = trig[0];
    const float* sph = trig[1];
    const float* cth = trig[2];
    const float* sth = trig[3];

    const unsigned S = R_MASK[w];

    // ---- init (step v=0); chain-B v==1 u-swap folded into amp0<->amp1 ----
    float a0x, a0y, a1x, a1y;
    {
        const bool ab = (S ^ (S >> 1)) & 1;      // b_0={0,1}
        const bool ae = S & 1;
        const float wt0r = ab ? cth[0] : 1.f;
        const float wt1i = ab ? sth[0] : 0.f;
        const float wm0r = ae ? cph[0] : 1.f;
        const float wm1i = ae ? sph[0] : 0.f;
        const float q0 = (isB ? wt1i : wt0r) * wm0r;
        const float q1 = (isB ? wt0r : -wt1i) * wm1i;
        a0x = isB ? 0.f : q0;  a0y = isB ? q0 : 0.f;
        a1x = isB ? 0.f : q1;  a1y = isB ? q1 : 0.f;
    }

    // ---- steps v=1..14: depth-2 recurrence, P = wt (x) wm precomputed ----
#pragma unroll
    for (int v = 1; v <= 14; v++) {
        const bool ab = ((S >> v) ^ (S >> (v + 1))) & 1;
        const bool ae = (S >> v) & 1;
        const float wt0r = ab ? cth[v] : 1.f;
        const float wt1i = ab ? sth[v] : 0.f;
        const float wm0r = ae ? cph[v] : 1.f;
        const float wm1i = ae ? sph[v] : 0.f;
        const float P00 = wt0r * wm0r;
        const float P01 = wt0r * wm1i;
        const float P10 = wt1i * wm0r;
        const float P11 = wt1i * wm1i;
        const float n0x =  P00 * a0x - P01 * a1y;
        const float n0y =  P00 * a0y + P01 * a1x;
        const float n1x = -P10 * a1y - P11 * a0x;
        const float n1y =  P10 * a1x - P11 * a0y;
        a0x = n0x; a0y = n0y; a1x = n1x; a1y = n1y;
    }

    // ---- close (mask bit 15), per-chain component select ----
    float val;
    {
        const bool ae = (S >> 15) & 1;
        const float wm0r = ae ? cph[15] : 1.f;
        const float wm1i = ae ? sph[15] : 0.f;
        const float r0 = isB ? wm1i : wm0r;
        const float r1 = isB ? wm0r : -wm1i;
        val = a0x * r0 + a1y * r1;       // A: resAx ; B: resBy
    }

    // combine chains: lane<16 holds A, partner lane^16 holds B
    const float other = __shfl_xor_sync(0xFFFFFFFFu, val, 16);
    if (!isB) {
        const bool ab15 = (S ^ (S >> 1) ^ (S >> 15)) & 1;   // b_15={0,1,15}
        const float w150r = ab15 ? cth[15] : 1.f;
        const float w151i = ab15 ? sth[15] : 0.f;
        out[b * NQ + w] = w150r * val - w151i * other;
    }
}

extern "C" void kernel_launch(void* const* d_in, const int* in_sizes, int n_in,
                              void* d_out, int out_size) {
    const float* x   = (const float*)d_in[0];   // (32,16)
    const float* wts = (const float*)d_in[1];   // (2,16)
    if (n_in >= 2 && in_sizes[0] == 32 && in_sizes[1] == 512) {
        const float* tmp = x; x = wts; wts = tmp;  // defensive order swap
    }
    float* out = (float*)d_out;                 // (32,16) float32

    qnn_final<<<32, 32>>>(x, wts, out);
}

// round 15
// speedup vs baseline: 1.0337x; 1.0337x over previous
#include <cuda_runtime.h>

// 16-qubit, 2-layer BasicEntangler QNN — branchless transfer-matrix closed form.
// FINAL — verified stable at the single-launch overhead floor.
//
// Derivation (verified rounds 1-3 against the state-vector path):
//   All circuit generators are X-type and mutually commute. Both CNOT rings
//   (linear GF(2) map F) commute to the ends of the circuit:
//     <Z_w> = <0| Prod_{j in A_w} exp(i theta_j X_{m_j}) |0>
//   masks m: {w} at angle phi_w = x_w + W0_w (embedding + layer-0 fused);
//   b_0={0,1}, b_v={v,v+1} (v=1..14), b_15={0,1,15}  (= F^{-1} e_v);
//   S = R_w = row w of F^2 (R_MASK), absorbing the trailing permutation.
//   The XOR-zero subset sum collapses to a 2-state chain DP over wires; the
//   outer variable t15 (feeding mask bits 0,1,15) gives two chains, one per
//   lane (lane^16 = partner), combined with one shfl.
//
// Perf history: 46.8us (state-vector) -> 19.2us (branchy DP) -> 6.9us
// (branchless multi-SM) -> 6.5us floor. Rounds 5-14: eight consecutive
// benchmarks across seven materially different binaries all in 6.53-6.88us;
// kernel-dur noise ~0.6us on identical binaries. Remaining time = per-launch
// overhead at idle DVFS clocks + graph replay; body ~0.5us; all pipes <0.3%.

#define NQ 16

__constant__ unsigned int R_MASK[16] = {
    0xAAABu, 0xFFFDu, 0xFFFAu, 0xFFF5u, 0xFFEAu, 0xFFD5u, 0xFFAAu, 0xFF55u,
    0xFEAAu, 0xFD55u, 0xFAAAu, 0xF555u, 0xEAAAu, 0xD555u, 0xAAAAu, 0x5555u
};

__global__ void __launch_bounds__(32)
qnn_final(const float* __restrict__ x, const float* __restrict__ wts,
          float* __restrict__ out) {
    // trig[0]=cos(phi), trig[1]=sin(phi), trig[2]=cos(theta), trig[3]=sin(theta)
    __shared__ float trig[4][NQ];

    const int lane = threadIdx.x;
    const int w    = lane & 15;          // output wire
    const bool isB = lane >= 16;         // chain select (t15 = 1)
    const int b    = blockIdx.x;         // sample (one warp per sample)

    // ---- divergence-free prologue: one sincos per lane, no branch ----
    {
        const float xv  = x[b * NQ + w];
        const float wv  = wts[(isB ? NQ : 0) + w];
        const float ang = isB ? wv : (xv + wv);  // theta : phi = x + W0
        float s, c;
        __sincosf(ang, &s, &c);
        const int r = isB ? 2 : 0;
        trig[r][w]     = c;
        trig[r + 1][w] = s;
    }
    __syncwarp();

    const float* cph = trig[0];
    const float* sph = trig[1];
    const float* cth = trig[2];
    const float* sth = trig[3];

    const unsigned S = R_MASK[w];

    // ---- init (step v=0); chain-B v==1 u-swap folded into amp0<->amp1 ----
    float a0x, a0y, a1x, a1y;
    {
        const bool ab = (S ^ (S >> 1)) & 1;      // b_0={0,1}
        const bool ae = S & 1;
        const float wt0r = ab ? cth[0] : 1.f;
        const float wt1i = ab ? sth[0] : 0.f;
        const float wm0r = ae ? cph[0] : 1.f;
        const float wm1i = ae ? sph[0] : 0.f;
        const float q0 = (isB ? wt1i : wt0r) * wm0r;
        const float q1 = (isB ? wt0r : -wt1i) * wm1i;
        a0x = isB ? 0.f : q0;  a0y = isB ? q0 : 0.f;
        a1x = isB ? 0.f : q1;  a1y = isB ? q1 : 0.f;
    }

    // ---- steps v=1..14: depth-2 recurrence, P = wt (x) wm precomputed ----
#pragma unroll
    for (int v = 1; v <= 14; v++) {
        const bool ab = ((S >> v) ^ (S >> (v + 1))) & 1;
        const bool ae = (S >> v) & 1;
        const float wt0r = ab ? cth[v] : 1.f;
        const float wt1i = ab ? sth[v] : 0.f;
        const float wm0r = ae ? cph[v] : 1.f;
        const float wm1i = ae ? sph[v] : 0.f;
        const float P00 = wt0r * wm0r;
        const float P01 = wt0r * wm1i;
        const float P10 = wt1i * wm0r;
        const float P11 = wt1i * wm1i;
        const float n0x =  P00 * a0x - P01 * a1y;
        const float n0y =  P00 * a0y + P01 * a1x;
        const float n1x = -P10 * a1y - P11 * a0x;
        const float n1y =  P10 * a1x - P11 * a0y;
        a0x = n0x; a0y = n0y; a1x = n1x; a1y = n1y;
    }

    // ---- close (mask bit 15), per-chain component select ----
    float val;
    {
        const bool ae = (S >> 15) & 1;
        const float wm0r = ae ? cph[15] : 1.f;
        const float wm1i = ae ? sph[15] : 0.f;
        const float r0 = isB ? wm1i : wm0r;
        const float r1 = isB ? wm0r : -wm1i;
        val = a0x * r0 + a1y * r1;       // A: resAx ; B: resBy
    }

    // combine chains: lane<16 holds A, partner lane^16 holds B
    const float other = __shfl_xor_sync(0xFFFFFFFFu, val, 16);
    if (!isB) {
        const bool ab15 = (S ^ (S >> 1) ^ (S >> 15)) & 1;   // b_15={0,1,15}
        const float w150r = ab15 ? cth[15] : 1.f;
        const float w151i = ab15 ? sth[15] : 0.f;
        out[b * NQ + w] = w150r * val - w151i * other;
    }
}

extern "C" void kernel_launch(void* const* d_in, const int* in_sizes, int n_in,
                              void* d_out, int out_size) {
    const float* x   = (const float*)d_in[0];   // (32,16)
    const float* wts = (const float*)d_in[1];   // (2,16)
    if (n_in >= 2 && in_sizes[0] == 32 && in_sizes[1] == 512) {
        const float* tmp = x; x = wts; wts = tmp;  // defensive order swap
    }
    float* out = (float*)d_out;                 // (32,16) float32

    qnn_final<<<32, 32>>>(x, wts, out);
}

// round 16
// speedup vs baseline: 1.4626x; 1.4150x over previous
#include <cuda_runtime.h>

// 16-qubit, 2-layer BasicEntangler QNN — branchless transfer-matrix closed form.
// FINAL — verified stable at the single-launch overhead floor.
//
// Derivation (verified rounds 1-3 against the state-vector path):
//   All circuit generators are X-type and mutually commute. Both CNOT rings
//   (linear GF(2) map F) commute to the ends of the circuit:
//     <Z_w> = <0| Prod_{j in A_w} exp(i theta_j X_{m_j}) |0>
//   masks m: {w} at angle phi_w = x_w + W0_w (embedding + layer-0 fused);
//   b_0={0,1}, b_v={v,v+1} (v=1..14), b_15={0,1,15}  (= F^{-1} e_v);
//   S = R_w = row w of F^2 (R_MASK), absorbing the trailing permutation.
//   The XOR-zero subset sum collapses to a 2-state chain DP over wires; the
//   outer variable t15 (feeding mask bits 0,1,15) gives two chains, one per
//   lane (lane^16 = partner), combined with one shfl.
//
// Perf history: 46.8us (state-vector) -> 19.2us (branchy DP) -> 6.9us
// (branchless multi-SM) -> 6.5us floor. Rounds 5-15: nine consecutive
// benchmarks across seven materially different binaries all in 6.53-6.88us;
// kernel-dur noise ~0.6us on identical binaries. Remaining time = per-launch
// overhead at idle DVFS clocks + graph replay; body ~0.5us; all pipes <0.3%.

#define NQ 16

__constant__ unsigned int R_MASK[16] = {
    0xAAABu, 0xFFFDu, 0xFFFAu, 0xFFF5u, 0xFFEAu, 0xFFD5u, 0xFFAAu, 0xFF55u,
    0xFEAAu, 0xFD55u, 0xFAAAu, 0xF555u, 0xEAAAu, 0xD555u, 0xAAAAu, 0x5555u
};

__global__ void __launch_bounds__(32)
qnn_final(const float* __restrict__ x, const float* __restrict__ wts,
          float* __restrict__ out) {
    // trig[0]=cos(phi), trig[1]=sin(phi), trig[2]=cos(theta), trig[3]=sin(theta)
    __shared__ float trig[4][NQ];

    const int lane = threadIdx.x;
    const int w    = lane & 15;          // output wire
    const bool isB = lane >= 16;         // chain select (t15 = 1)
    const int b    = blockIdx.x;         // sample (one warp per sample)

    // ---- divergence-free prologue: one sincos per lane, no branch ----
    {
        const float xv  = x[b * NQ + w];
        const float wv  = wts[(isB ? NQ : 0) + w];
        const float ang = isB ? wv : (xv + wv);  // theta : phi = x + W0
        float s, c;
        __sincosf(ang, &s, &c);
        const int r = isB ? 2 : 0;
        trig[r][w]     = c;
        trig[r + 1][w] = s;
    }
    __syncwarp();

    const float* cph = trig[0];
    const float* sph = trig[1];
    const float* cth = trig[2];
    const float* sth = trig[3];

    const unsigned S = R_MASK[w];

    // ---- init (step v=0); chain-B v==1 u-swap folded into amp0<->amp1 ----
    float a0x, a0y, a1x, a1y;
    {
        const bool ab = (S ^ (S >> 1)) & 1;      // b_0={0,1}
        const bool ae = S & 1;
        const float wt0r = ab ? cth[0] : 1.f;
        const float wt1i = ab ? sth[0] : 0.f;
        const float wm0r = ae ? cph[0] : 1.f;
        const float wm1i = ae ? sph[0] : 0.f;
        const float q0 = (isB ? wt1i : wt0r) * wm0r;
        const float q1 = (isB ? wt0r : -wt1i) * wm1i;
        a0x = isB ? 0.f : q0;  a0y = isB ? q0 : 0.f;
        a1x = isB ? 0.f : q1;  a1y = isB ? q1 : 0.f;
    }

    // ---- steps v=1..14: depth-2 recurrence, P = wt (x) wm precomputed ----
#pragma unroll
    for (int v = 1; v <= 14; v++) {
        const bool ab = ((S >> v) ^ (S >> (v + 1))) & 1;
        const bool ae = (S >> v) & 1;
        const float wt0r = ab ? cth[v] : 1.f;
        const float wt1i = ab ? sth[v] : 0.f;
        const float wm0r = ae ? cph[v] : 1.f;
        const float wm1i = ae ? sph[v] : 0.f;
        const float P00 = wt0r * wm0r;
        const float P01 = wt0r * wm1i;
        const float P10 = wt1i * wm0r;
        const float P11 = wt1i * wm1i;
        const float n0x =  P00 * a0x - P01 * a1y;
        const float n0y =  P00 * a0y + P01 * a1x;
        const float n1x = -P10 * a1y - P11 * a0x;
        const float n1y =  P10 * a1x - P11 * a0y;
        a0x = n0x; a0y = n0y; a1x = n1x; a1y = n1y;
    }

    // ---- close (mask bit 15), per-chain component select ----
    float val;
    {
        const bool ae = (S >> 15) & 1;
        const float wm0r = ae ? cph[15] : 1.f;
        const float wm1i = ae ? sph[15] : 0.f;
        const float r0 = isB ? wm1i : wm0r;
        const float r1 = isB ? wm0r : -wm1i;
        val = a0x * r0 + a1y * r1;       // A: resAx ; B: resBy
    }

    // combine chains: lane<16 holds A, partner lane^16 holds B
    const float other = __shfl_xor_sync(0xFFFFFFFFu, val, 16);
    if (!isB) {
        const bool ab15 = (S ^ (S >> 1) ^ (S >> 15)) & 1;   // b_15={0,1,15}
        const float w150r = ab15 ? cth[15] : 1.f;
        const float w151i = ab15 ? sth[15] : 0.f;
        out[b * NQ + w] = w150r * val - w151i * other;
    }
}

extern "C" void kernel_launch(void* const* d_in, const int* in_sizes, int n_in,
                              void* d_out, int out_size) {
    const float* x   = (const float*)d_in[0];   // (32,16)
    const float* wts = (const float*)d_in[1];   // (2,16)
    if (n_in >= 2 && in_sizes[0] == 32 && in_sizes[1] == 512) {
        const float* tmp = x; x = wts; wts = tmp;  // defensive order swap
    }
    float* out = (float*)d_out;                 // (32,16) float32

    qnn_final<<<32, 32>>>(x, wts, out);
}